// round 5
// baseline (speedup 1.0000x reference)
#include <cuda_runtime.h>
#include <math.h>

#define SEQ 4096
#define DM 1024
#define NH 16
#define HD 64
#define WIN 512

// Scratch (allocation-free rule: __device__ globals)
__device__ float g_qkv[SEQ * 3 * DM];
__device__ float g_q[NH * SEQ * HD];
__device__ float g_k[NH * SEQ * HD];
__device__ float g_v[NH * SEQ * HD];
__device__ float g_att[SEQ * DM];
__device__ float g_cos[SEQ * 32];   // [l][p] cos table
__device__ float g_sin[SEQ * 32];   // [l][p] sin table

// ---------------------------------------------------------------------------
// SGEMM: C[M,N] = A[M,K] @ B[K,N], fp32, BM=BN=128, BK=16, 256 threads, 8x8/thr
// ---------------------------------------------------------------------------
__global__ __launch_bounds__(256) void sgemm_kernel(
    const float* __restrict__ A, const float* __restrict__ B,
    float* __restrict__ C, int M, int N, int K)
{
    __shared__ float As[16][128];
    __shared__ float Bs[16][128];

    const int bx = blockIdx.x;
    const int by = blockIdx.y;
    const int tid = threadIdx.x;

    const int rowA = tid >> 2;
    const int colA = (tid & 3) * 4;
    const int rowB = tid >> 5;
    const int colB = (tid & 31) * 4;

    const int tr = (tid >> 4) * 8;
    const int tc = (tid & 15) * 8;

    float acc[8][8];
#pragma unroll
    for (int u = 0; u < 8; u++)
#pragma unroll
        for (int v = 0; v < 8; v++) acc[u][v] = 0.f;

    const float* Abase = A + (size_t)(by * 128) * K;
    const float* Bbase = B + bx * 128;

    for (int kt = 0; kt < K; kt += 16) {
        float4 a0 = *(const float4*)(Abase + (size_t)rowA        * K + kt + colA);
        float4 a1 = *(const float4*)(Abase + (size_t)(rowA + 64) * K + kt + colA);
        float4 b0 = *(const float4*)(Bbase + (size_t)(kt + rowB)     * N + colB);
        float4 b1 = *(const float4*)(Bbase + (size_t)(kt + rowB + 8) * N + colB);

        __syncthreads();
        As[colA + 0][rowA] = a0.x;  As[colA + 1][rowA] = a0.y;
        As[colA + 2][rowA] = a0.z;  As[colA + 3][rowA] = a0.w;
        As[colA + 0][rowA + 64] = a1.x;  As[colA + 1][rowA + 64] = a1.y;
        As[colA + 2][rowA + 64] = a1.z;  As[colA + 3][rowA + 64] = a1.w;
        *(float4*)(&Bs[rowB][colB])     = b0;
        *(float4*)(&Bs[rowB + 8][colB]) = b1;
        __syncthreads();

#pragma unroll
        for (int kk = 0; kk < 16; kk++) {
            float ra[8], rb[8];
#pragma unroll
            for (int u = 0; u < 8; u++) ra[u] = As[kk][tr + u];
#pragma unroll
            for (int v = 0; v < 8; v++) rb[v] = Bs[kk][tc + v];
#pragma unroll
            for (int u = 0; u < 8; u++)
#pragma unroll
                for (int v = 0; v < 8; v++) acc[u][v] = fmaf(ra[u], rb[v], acc[u][v]);
        }
    }

    float* Cbase = C + (size_t)(by * 128 + tr) * N + bx * 128 + tc;
#pragma unroll
    for (int u = 0; u < 8; u++) {
        *(float4*)(Cbase + (size_t)u * N)     = make_float4(acc[u][0], acc[u][1], acc[u][2], acc[u][3]);
        *(float4*)(Cbase + (size_t)u * N + 4) = make_float4(acc[u][4], acc[u][5], acc[u][6], acc[u][7]);
    }
}

// ---------------------------------------------------------------------------
// RoPE tables: one thread per (l, p), 131K threads total.
// Keeps the exact powf/sincosf sequence of the previously-passing kernel.
// ---------------------------------------------------------------------------
__global__ __launch_bounds__(256) void rope_table_kernel()
{
    int idx = blockIdx.x * blockDim.x + threadIdx.x;
    if (idx >= SEQ * 32) return;
    int p = idx & 31;
    int l = idx >> 5;

    float inv_freq = powf(10000.0f, -(2.0f * (float)p) / 64.0f);
    float ang = (float)l * inv_freq;
    float s, c;
    sincosf(ang, &s, &c);
    g_cos[idx] = c;
    g_sin[idx] = s;
}

// ---------------------------------------------------------------------------
// RoPE + scatter (table-driven, pure bandwidth)
// ---------------------------------------------------------------------------
__global__ __launch_bounds__(256) void rope_scatter_kernel(const float* __restrict__ qkv)
{
    int idx = blockIdx.x * blockDim.x + threadIdx.x;
    if (idx >= SEQ * NH * 32) return;
    int p = idx & 31;
    int h = (idx >> 5) & (NH - 1);
    int l = idx >> 9;

    float c = g_cos[l * 32 + p];
    float s = g_sin[l * 32 + p];

    const float* src = qkv + (size_t)l * (3 * DM);
    int col = h * HD + 2 * p;
    float q0 = src[col],          q1 = src[col + 1];
    float k0 = src[DM + col],     k1 = src[DM + col + 1];
    float v0 = src[2 * DM + col], v1 = src[2 * DM + col + 1];

    size_t dst = (size_t)(h * SEQ + l) * HD + 2 * p;
    g_q[dst]     = q0 * c - q1 * s;
    g_q[dst + 1] = q1 * c + q0 * s;
    g_k[dst]     = k0 * c - k1 * s;
    g_k[dst + 1] = k1 * c + k0 * s;
    g_v[dst]     = v0;
    g_v[dst + 1] = v1;
}

// ---------------------------------------------------------------------------
// Tiled flash attention: block = 256 thr = 64-query tile of one head.
// ---------------------------------------------------------------------------
__global__ __launch_bounds__(256) void attn_kernel(
    const float* __restrict__ Q, const float* __restrict__ K,
    const float* __restrict__ V, float* __restrict__ O)
{
    __shared__ float Qs[64][64];   // [d][q], prescaled by 1/8
    __shared__ float KP[64][64];   // QK phase: [d][k] ; PV phase: P[q][k]
    __shared__ float Vs[64][64];   // [k][d]

    const int h  = blockIdx.y;
    const int r0 = blockIdx.x * 64;
    const int tid = threadIdx.x;
    const int tx = tid & 15;
    const int ty = tid >> 4;
    const int ty4 = ty * 4;
    const int tx4 = tx * 4;

    {
        const int row  = tid >> 2;
        const int dbase = (tid & 3) * 16;
        const float* qrow = Q + ((size_t)(h * SEQ + r0 + row)) * HD + dbase;
#pragma unroll
        for (int u = 0; u < 4; u++) {
            float4 t4 = *(const float4*)(qrow + 4 * u);
            Qs[dbase + 4 * u + 0][row] = t4.x * 0.125f;
            Qs[dbase + 4 * u + 1][row] = t4.y * 0.125f;
            Qs[dbase + 4 * u + 2][row] = t4.z * 0.125f;
            Qs[dbase + 4 * u + 3][row] = t4.w * 0.125f;
        }
    }

    float o[4][4];
    float m[4], l[4];
#pragma unroll
    for (int i = 0; i < 4; i++) {
        m[i] = -1e30f; l[i] = 0.f;
#pragma unroll
        for (int j = 0; j < 4; j++) o[i][j] = 0.f;
    }

    const int t_hi = r0 >> 6;
    int jmin = r0 - (WIN - 1); if (jmin < 0) jmin = 0;
    const int t_lo = jmin >> 6;

    for (int t = t_hi; t >= t_lo; t--) {
        const int c0 = t * 64;
        __syncthreads();

        {
            const int row  = tid >> 2;
            const int dbase = (tid & 3) * 16;
            const float* krow = K + ((size_t)(h * SEQ + c0 + row)) * HD + dbase;
            const float* vrow = V + ((size_t)(h * SEQ + c0 + row)) * HD + dbase;
#pragma unroll
            for (int u = 0; u < 4; u++) {
                float4 t4 = *(const float4*)(krow + 4 * u);
                KP[dbase + 4 * u + 0][row] = t4.x;
                KP[dbase + 4 * u + 1][row] = t4.y;
                KP[dbase + 4 * u + 2][row] = t4.z;
                KP[dbase + 4 * u + 3][row] = t4.w;
                *(float4*)(&Vs[row][dbase + 4 * u]) = *(const float4*)(vrow + 4 * u);
            }
        }
        __syncthreads();

        float s[4][4];
#pragma unroll
        for (int i = 0; i < 4; i++)
#pragma unroll
            for (int j = 0; j < 4; j++) s[i][j] = 0.f;

#pragma unroll 4
        for (int d = 0; d < 64; d++) {
            float a[4], b[4];
            *(float4*)a = *(const float4*)&Qs[d][ty4];
            *(float4*)b = *(const float4*)&KP[d][tx4];
#pragma unroll
            for (int i = 0; i < 4; i++)
#pragma unroll
                for (int j = 0; j < 4; j++)
                    s[i][j] = fmaf(a[i], b[j], s[i][j]);
        }

        if (t == t_hi || (t_hi - t) >= 8) {
#pragma unroll
            for (int i = 0; i < 4; i++) {
                int gq = r0 + ty4 + i;
#pragma unroll
                for (int j = 0; j < 4; j++) {
                    int gk = c0 + tx4 + j;
                    bool valid = (gk <= gq) && (gq - gk < WIN);
                    if (!valid) s[i][j] = -1e30f;
                }
            }
        }

        float p[4][4];
#pragma unroll
        for (int i = 0; i < 4; i++) {
            float mx = fmaxf(fmaxf(s[i][0], s[i][1]), fmaxf(s[i][2], s[i][3]));
#pragma unroll
            for (int off = 8; off >= 1; off >>= 1)
                mx = fmaxf(mx, __shfl_xor_sync(0xFFFFFFFFu, mx, off));
            float newm = fmaxf(m[i], mx);
            float corr = __expf(m[i] - newm);
            float rs = 0.f;
#pragma unroll
            for (int j = 0; j < 4; j++) {
                p[i][j] = __expf(s[i][j] - newm);
                rs += p[i][j];
            }
#pragma unroll
            for (int off = 8; off >= 1; off >>= 1)
                rs += __shfl_xor_sync(0xFFFFFFFFu, rs, off);
            l[i] = l[i] * corr + rs;
            m[i] = newm;
#pragma unroll
            for (int j = 0; j < 4; j++) o[i][j] *= corr;
        }

        __syncthreads();

#pragma unroll
        for (int i = 0; i < 4; i++)
            *(float4*)&KP[ty4 + i][tx4] = make_float4(p[i][0], p[i][1], p[i][2], p[i][3]);
        __syncthreads();

#pragma unroll 4
        for (int k = 0; k < 64; k += 4) {
            float4 b0 = *(const float4*)&Vs[k + 0][tx4];
            float4 b1 = *(const float4*)&Vs[k + 1][tx4];
            float4 b2 = *(const float4*)&Vs[k + 2][tx4];
            float4 b3 = *(const float4*)&Vs[k + 3][tx4];
#pragma unroll
            for (int i = 0; i < 4; i++) {
                float4 a = *(const float4*)&KP[ty4 + i][k];
                o[i][0] = fmaf(a.x, b0.x, o[i][0]);
                o[i][1] = fmaf(a.x, b0.y, o[i][1]);
                o[i][2] = fmaf(a.x, b0.z, o[i][2]);
                o[i][3] = fmaf(a.x, b0.w, o[i][3]);
                o[i][0] = fmaf(a.y, b1.x, o[i][0]);
                o[i][1] = fmaf(a.y, b1.y, o[i][1]);
                o[i][2] = fmaf(a.y, b1.z, o[i][2]);
                o[i][3] = fmaf(a.y, b1.w, o[i][3]);
                o[i][0] = fmaf(a.z, b2.x, o[i][0]);
                o[i][1] = fmaf(a.z, b2.y, o[i][1]);
                o[i][2] = fmaf(a.z, b2.z, o[i][2]);
                o[i][3] = fmaf(a.z, b2.w, o[i][3]);
                o[i][0] = fmaf(a.w, b3.x, o[i][0]);
                o[i][1] = fmaf(a.w, b3.y, o[i][1]);
                o[i][2] = fmaf(a.w, b3.z, o[i][2]);
                o[i][3] = fmaf(a.w, b3.w, o[i][3]);
            }
        }
    }

#pragma unroll
    for (int i = 0; i < 4; i++) {
        float inv = 1.0f / l[i];
        float4 r = make_float4(o[i][0] * inv, o[i][1] * inv, o[i][2] * inv, o[i][3] * inv);
        *(float4*)(O + (size_t)(r0 + ty4 + i) * DM + h * HD + tx4) = r;
    }
}

// ---------------------------------------------------------------------------
extern "C" void kernel_launch(void* const* d_in, const int* in_sizes, int n_in,
                              void* d_out, int out_size)
{
    const float* x     = (const float*)d_in[0];
    const float* w_qkv = (const float*)d_in[1];
    const float* w_out = (const float*)d_in[2];
    float* out = (float*)d_out;

    float *p_qkv, *p_q, *p_k, *p_v, *p_att;
    cudaGetSymbolAddress((void**)&p_qkv, g_qkv);
    cudaGetSymbolAddress((void**)&p_q,   g_q);
    cudaGetSymbolAddress((void**)&p_k,   g_k);
    cudaGetSymbolAddress((void**)&p_v,   g_v);
    cudaGetSymbolAddress((void**)&p_att, g_att);

    // RoPE tables (independent of GEMM1 -> issue first, overlaps on stream)
    rope_table_kernel<<<(SEQ * 32 + 255) / 256, 256>>>();

    sgemm_kernel<<<dim3(3 * DM / 128, SEQ / 128), 256>>>(x, w_qkv, p_qkv, SEQ, 3 * DM, DM);

    int total = SEQ * NH * 32;
    rope_scatter_kernel<<<(total + 255) / 256, 256>>>(p_qkv);

    attn_kernel<<<dim3(SEQ / 64, NH), 256>>>(p_q, p_k, p_v, p_att);

    sgemm_kernel<<<dim3(DM / 128, SEQ / 128), 256>>>(p_att, w_out, out, SEQ, DM, DM);
}

// round 9
// speedup vs baseline: 1.5535x; 1.5535x over previous
#include <cuda_runtime.h>
#include <cuda_bf16.h>
#include <math.h>
#include <cstdint>

#define SEQ 4096
#define DM 1024
#define NH 16
#define HD 64
#define WIN 512

// Scratch (allocation-free rule: __device__ globals)
__device__ float g_qkv[SEQ * 3 * DM];
__device__ float g_q[NH * SEQ * HD];
__device__ float g_k[NH * SEQ * HD];
__device__ float g_v[NH * SEQ * HD];
__device__ float g_att[SEQ * DM];
__device__ float g_cos[SEQ * 32];
__device__ float g_sin[SEQ * 32];

// ===========================================================================
// HMMA split-bf16 GEMM: C[M,N] = A[M,K] @ B[K,N], fp32 in/out.
// A,B -> bf16 hi+lo; D = Ah*Bh + Ah*Bl + Al*Bh (fp32 accum in registers).
// CTA: 256 threads (8 warps, 4m x 2n), 128x128 tile, K-chunk 32.
// mma.sync.m16n8k16 bf16 (plain PTX -- compiles for sm_103 base target).
// ===========================================================================

#define MMA16816(d, a, b)                                              \
    asm volatile(                                                      \
        "mma.sync.aligned.m16n8k16.row.col.f32.bf16.bf16.f32 "         \
        "{%0,%1,%2,%3}, {%4,%5,%6,%7}, {%8,%9}, {%0,%1,%2,%3};"        \
        : "+f"(d[0]), "+f"(d[1]), "+f"(d[2]), "+f"(d[3])               \
        : "r"(a[0]), "r"(a[1]), "r"(a[2]), "r"(a[3]),                  \
          "r"(b[0]), "r"(b[1]))

#define SPAD 40   // bf16 elements per smem row (20 words -> conflict-free frags)

__global__ __launch_bounds__(256) void gemm_mma_kernel(
    const float* __restrict__ A, const float* __restrict__ B,
    float* __restrict__ C, int M, int N, int K)
{
    __shared__ __nv_bfloat16 Ah[128 * SPAD];
    __shared__ __nv_bfloat16 Al[128 * SPAD];
    __shared__ __nv_bfloat16 Bh[128 * SPAD];
    __shared__ __nv_bfloat16 Bl[128 * SPAD];

    const int tid  = threadIdx.x;
    const int lane = tid & 31;
    const int w    = tid >> 5;
    const int g    = lane >> 2;      // 0..7
    const int tg   = lane & 3;       // 0..3
    const int wm   = w & 3;          // m-warp (32 rows each)
    const int wn   = w >> 2;         // n-warp (64 cols each)
    const int m0   = blockIdx.y * 128;
    const int n0   = blockIdx.x * 128;

    float acc[2][8][4];
#pragma unroll
    for (int mt = 0; mt < 2; mt++)
#pragma unroll
        for (int nt = 0; nt < 8; nt++)
#pragma unroll
            for (int r = 0; r < 4; r++) acc[mt][nt][r] = 0.f;

    const int a_f2    = tid & 15;        // float2 column (k/2)
    const int a_rbase = tid >> 4;        // 0..15
    const int b_n     = tid & 127;
    const int b_kb    = tid >> 7;        // 0..1

    for (int kt = 0; kt < K; kt += 32) {
        __syncthreads();   // previous chunk's frag reads complete

        // ---- A chunk [128 m][32 k] -> Ah/Al [m][k] ----
#pragma unroll
        for (int p = 0; p < 8; p++) {
            int row = p * 16 + a_rbase;
            float2 v = *(const float2*)(A + (size_t)(m0 + row) * K + kt + a_f2 * 2);
            __nv_bfloat16 h0 = __float2bfloat16(v.x);
            __nv_bfloat16 h1 = __float2bfloat16(v.y);
            __nv_bfloat16 l0 = __float2bfloat16(v.x - __bfloat162float(h0));
            __nv_bfloat16 l1 = __float2bfloat16(v.y - __bfloat162float(h1));
            __nv_bfloat162 hh; hh.x = h0; hh.y = h1;
            __nv_bfloat162 ll; ll.x = l0; ll.y = l1;
            *(__nv_bfloat162*)&Ah[row * SPAD + a_f2 * 2] = hh;
            *(__nv_bfloat162*)&Al[row * SPAD + a_f2 * 2] = ll;
        }

        // ---- B chunk [32 k][128 n] -> Bh/Bl transposed [n][k] ----
#pragma unroll
        for (int p = 0; p < 16; p++) {
            int k = p * 2 + b_kb;
            float v = B[(size_t)(kt + k) * N + n0 + b_n];
            __nv_bfloat16 h = __float2bfloat16(v);
            Bh[b_n * SPAD + k] = h;
            Bl[b_n * SPAD + k] = __float2bfloat16(v - __bfloat162float(h));
        }
        __syncthreads();

        // ---- MMA: 2 k-steps of 16 ----
#pragma unroll
        for (int ks = 0; ks < 2; ks++) {
            const int kk = ks * 16 + tg * 2;
            uint32_t bh[8][2], bl[8][2];
#pragma unroll
            for (int nt = 0; nt < 8; nt++) {
                int nn = wn * 64 + nt * 8 + g;
                bh[nt][0] = *(uint32_t*)&Bh[nn * SPAD + kk];
                bh[nt][1] = *(uint32_t*)&Bh[nn * SPAD + kk + 8];
                bl[nt][0] = *(uint32_t*)&Bl[nn * SPAD + kk];
                bl[nt][1] = *(uint32_t*)&Bl[nn * SPAD + kk + 8];
            }
#pragma unroll
            for (int mt = 0; mt < 2; mt++) {
                const int rb = wm * 32 + mt * 16;
                uint32_t ah[4], al[4];
                ah[0] = *(uint32_t*)&Ah[(rb + g)     * SPAD + kk];
                ah[1] = *(uint32_t*)&Ah[(rb + g + 8) * SPAD + kk];
                ah[2] = *(uint32_t*)&Ah[(rb + g)     * SPAD + kk + 8];
                ah[3] = *(uint32_t*)&Ah[(rb + g + 8) * SPAD + kk + 8];
                al[0] = *(uint32_t*)&Al[(rb + g)     * SPAD + kk];
                al[1] = *(uint32_t*)&Al[(rb + g + 8) * SPAD + kk];
                al[2] = *(uint32_t*)&Al[(rb + g)     * SPAD + kk + 8];
                al[3] = *(uint32_t*)&Al[(rb + g + 8) * SPAD + kk + 8];
#pragma unroll
                for (int nt = 0; nt < 8; nt++) {
                    MMA16816(acc[mt][nt], ah, bh[nt]);
                    MMA16816(acc[mt][nt], ah, bl[nt]);
                    MMA16816(acc[mt][nt], al, bh[nt]);
                }
            }
        }
    }

    // ---- epilogue: direct float2 stores ----
#pragma unroll
    for (int mt = 0; mt < 2; mt++) {
        const int row = m0 + wm * 32 + mt * 16 + g;
#pragma unroll
        for (int nt = 0; nt < 8; nt++) {
            const int col = n0 + wn * 64 + nt * 8 + tg * 2;
            *(float2*)(C + (size_t)row * N + col) =
                make_float2(acc[mt][nt][0], acc[mt][nt][1]);
            *(float2*)(C + (size_t)(row + 8) * N + col) =
                make_float2(acc[mt][nt][2], acc[mt][nt][3]);
        }
    }
}

// ---------------------------------------------------------------------------
// RoPE tables
// ---------------------------------------------------------------------------
__global__ __launch_bounds__(256) void rope_table_kernel()
{
    int idx = blockIdx.x * blockDim.x + threadIdx.x;
    if (idx >= SEQ * 32) return;
    int p = idx & 31;
    int l = idx >> 5;
    float inv_freq = powf(10000.0f, -(2.0f * (float)p) / 64.0f);
    float ang = (float)l * inv_freq;
    float s, c;
    sincosf(ang, &s, &c);
    g_cos[idx] = c;
    g_sin[idx] = s;
}

// ---------------------------------------------------------------------------
// RoPE + scatter (table-driven)
// ---------------------------------------------------------------------------
__global__ __launch_bounds__(256) void rope_scatter_kernel(const float* __restrict__ qkv)
{
    int idx = blockIdx.x * blockDim.x + threadIdx.x;
    if (idx >= SEQ * NH * 32) return;
    int p = idx & 31;
    int h = (idx >> 5) & (NH - 1);
    int l = idx >> 9;

    float c = g_cos[l * 32 + p];
    float s = g_sin[l * 32 + p];

    const float* src = qkv + (size_t)l * (3 * DM);
    int col = h * HD + 2 * p;
    float q0 = src[col],          q1 = src[col + 1];
    float k0 = src[DM + col],     k1 = src[DM + col + 1];
    float v0 = src[2 * DM + col], v1 = src[2 * DM + col + 1];

    size_t dst = (size_t)(h * SEQ + l) * HD + 2 * p;
    g_q[dst]     = q0 * c - q1 * s;
    g_q[dst + 1] = q1 * c + q0 * s;
    g_k[dst]     = k0 * c - k1 * s;
    g_k[dst + 1] = k1 * c + k0 * s;
    g_v[dst]     = v0;
    g_v[dst + 1] = v1;
}

// ---------------------------------------------------------------------------
// Tiled flash attention (unchanged)
// ---------------------------------------------------------------------------
__global__ __launch_bounds__(256) void attn_kernel(
    const float* __restrict__ Q, const float* __restrict__ K,
    const float* __restrict__ V, float* __restrict__ O)
{
    __shared__ float Qs[64][64];
    __shared__ float KP[64][64];
    __shared__ float Vs[64][64];

    const int h  = blockIdx.y;
    const int r0 = blockIdx.x * 64;
    const int tid = threadIdx.x;
    const int tx = tid & 15;
    const int ty = tid >> 4;
    const int ty4 = ty * 4;
    const int tx4 = tx * 4;

    {
        const int row  = tid >> 2;
        const int dbase = (tid & 3) * 16;
        const float* qrow = Q + ((size_t)(h * SEQ + r0 + row)) * HD + dbase;
#pragma unroll
        for (int u = 0; u < 4; u++) {
            float4 t4 = *(const float4*)(qrow + 4 * u);
            Qs[dbase + 4 * u + 0][row] = t4.x * 0.125f;
            Qs[dbase + 4 * u + 1][row] = t4.y * 0.125f;
            Qs[dbase + 4 * u + 2][row] = t4.z * 0.125f;
            Qs[dbase + 4 * u + 3][row] = t4.w * 0.125f;
        }
    }

    float o[4][4];
    float m[4], l[4];
#pragma unroll
    for (int i = 0; i < 4; i++) {
        m[i] = -1e30f; l[i] = 0.f;
#pragma unroll
        for (int j = 0; j < 4; j++) o[i][j] = 0.f;
    }

    const int t_hi = r0 >> 6;
    int jmin = r0 - (WIN - 1); if (jmin < 0) jmin = 0;
    const int t_lo = jmin >> 6;

    for (int t = t_hi; t >= t_lo; t--) {
        const int c0 = t * 64;
        __syncthreads();

        {
            const int row  = tid >> 2;
            const int dbase = (tid & 3) * 16;
            const float* krow = K + ((size_t)(h * SEQ + c0 + row)) * HD + dbase;
            const float* vrow = V + ((size_t)(h * SEQ + c0 + row)) * HD + dbase;
#pragma unroll
            for (int u = 0; u < 4; u++) {
                float4 t4 = *(const float4*)(krow + 4 * u);
                KP[dbase + 4 * u + 0][row] = t4.x;
                KP[dbase + 4 * u + 1][row] = t4.y;
                KP[dbase + 4 * u + 2][row] = t4.z;
                KP[dbase + 4 * u + 3][row] = t4.w;
                *(float4*)(&Vs[row][dbase + 4 * u]) = *(const float4*)(vrow + 4 * u);
            }
        }
        __syncthreads();

        float s[4][4];
#pragma unroll
        for (int i = 0; i < 4; i++)
#pragma unroll
            for (int j = 0; j < 4; j++) s[i][j] = 0.f;

#pragma unroll 4
        for (int d = 0; d < 64; d++) {
            float a[4], b[4];
            *(float4*)a = *(const float4*)&Qs[d][ty4];
            *(float4*)b = *(const float4*)&KP[d][tx4];
#pragma unroll
            for (int i = 0; i < 4; i++)
#pragma unroll
                for (int j = 0; j < 4; j++)
                    s[i][j] = fmaf(a[i], b[j], s[i][j]);
        }

        if (t == t_hi || (t_hi - t) >= 8) {
#pragma unroll
            for (int i = 0; i < 4; i++) {
                int gq = r0 + ty4 + i;
#pragma unroll
                for (int j = 0; j < 4; j++) {
                    int gk = c0 + tx4 + j;
                    bool valid = (gk <= gq) && (gq - gk < WIN);
                    if (!valid) s[i][j] = -1e30f;
                }
            }
        }

        float p[4][4];
#pragma unroll
        for (int i = 0; i < 4; i++) {
            float mx = fmaxf(fmaxf(s[i][0], s[i][1]), fmaxf(s[i][2], s[i][3]));
#pragma unroll
            for (int off = 8; off >= 1; off >>= 1)
                mx = fmaxf(mx, __shfl_xor_sync(0xFFFFFFFFu, mx, off));
            float newm = fmaxf(m[i], mx);
            float corr = __expf(m[i] - newm);
            float rs = 0.f;
#pragma unroll
            for (int j = 0; j < 4; j++) {
                p[i][j] = __expf(s[i][j] - newm);
                rs += p[i][j];
            }
#pragma unroll
            for (int off = 8; off >= 1; off >>= 1)
                rs += __shfl_xor_sync(0xFFFFFFFFu, rs, off);
            l[i] = l[i] * corr + rs;
            m[i] = newm;
#pragma unroll
            for (int j = 0; j < 4; j++) o[i][j] *= corr;
        }

        __syncthreads();

#pragma unroll
        for (int i = 0; i < 4; i++)
            *(float4*)&KP[ty4 + i][tx4] = make_float4(p[i][0], p[i][1], p[i][2], p[i][3]);
        __syncthreads();

#pragma unroll 4
        for (int k = 0; k < 64; k += 4) {
            float4 b0 = *(const float4*)&Vs[k + 0][tx4];
            float4 b1 = *(const float4*)&Vs[k + 1][tx4];
            float4 b2 = *(const float4*)&Vs[k + 2][tx4];
            float4 b3 = *(const float4*)&Vs[k + 3][tx4];
#pragma unroll
            for (int i = 0; i < 4; i++) {
                float4 a = *(const float4*)&KP[ty4 + i][k];
                o[i][0] = fmaf(a.x, b0.x, o[i][0]);
                o[i][1] = fmaf(a.x, b0.y, o[i][1]);
                o[i][2] = fmaf(a.x, b0.z, o[i][2]);
                o[i][3] = fmaf(a.x, b0.w, o[i][3]);
                o[i][0] = fmaf(a.y, b1.x, o[i][0]);
                o[i][1] = fmaf(a.y, b1.y, o[i][1]);
                o[i][2] = fmaf(a.y, b1.z, o[i][2]);
                o[i][3] = fmaf(a.y, b1.w, o[i][3]);
                o[i][0] = fmaf(a.z, b2.x, o[i][0]);
                o[i][1] = fmaf(a.z, b2.y, o[i][1]);
                o[i][2] = fmaf(a.z, b2.z, o[i][2]);
                o[i][3] = fmaf(a.z, b2.w, o[i][3]);
                o[i][0] = fmaf(a.w, b3.x, o[i][0]);
                o[i][1] = fmaf(a.w, b3.y, o[i][1]);
                o[i][2] = fmaf(a.w, b3.z, o[i][2]);
                o[i][3] = fmaf(a.w, b3.w, o[i][3]);
            }
        }
    }

#pragma unroll
    for (int i = 0; i < 4; i++) {
        float inv = 1.0f / l[i];
        float4 r = make_float4(o[i][0] * inv, o[i][1] * inv, o[i][2] * inv, o[i][3] * inv);
        *(float4*)(O + (size_t)(r0 + ty4 + i) * DM + h * HD + tx4) = r;
    }
}

// ---------------------------------------------------------------------------
extern "C" void kernel_launch(void* const* d_in, const int* in_sizes, int n_in,
                              void* d_out, int out_size)
{
    const float* x     = (const float*)d_in[0];
    const float* w_qkv = (const float*)d_in[1];
    const float* w_out = (const float*)d_in[2];
    float* out = (float*)d_out;

    float *p_qkv, *p_q, *p_k, *p_v, *p_att;
    cudaGetSymbolAddress((void**)&p_qkv, g_qkv);
    cudaGetSymbolAddress((void**)&p_q,   g_q);
    cudaGetSymbolAddress((void**)&p_k,   g_k);
    cudaGetSymbolAddress((void**)&p_v,   g_v);
    cudaGetSymbolAddress((void**)&p_att, g_att);

    rope_table_kernel<<<(SEQ * 32 + 255) / 256, 256>>>();

    // 1) qkv = x @ w_qkv  (HMMA split-bf16)
    gemm_mma_kernel<<<dim3(3 * DM / 128, SEQ / 128), 256>>>(x, w_qkv, p_qkv, SEQ, 3 * DM, DM);

    int total = SEQ * NH * 32;
    rope_scatter_kernel<<<(total + 255) / 256, 256>>>(p_qkv);

    attn_kernel<<<dim3(SEQ / 64, NH), 256>>>(p_q, p_k, p_v, p_att);

    // 4) out = att @ w_out  (HMMA split-bf16)
    gemm_mma_kernel<<<dim3(DM / 128, SEQ / 128), 256>>>(p_att, w_out, out, SEQ, DM, DM);
}

// round 14
// speedup vs baseline: 2.0242x; 1.3030x over previous
#include <cuda_runtime.h>
#include <cuda_bf16.h>
#include <math.h>
#include <cstdint>

#define SEQ 4096
#define DM 1024
#define NH 16
#define HD 64
#define WIN 512

// Scratch (allocation-free rule: __device__ globals)
__device__ float g_qkv[SEQ * 3 * DM];
__device__ float g_att[SEQ * DM];
__device__ float g_cos[SEQ * 32];
__device__ float g_sin[SEQ * 32];
// split-bf16 Q/K/V, head-major [h][l][64]; Q prescaled by 1/8
__device__ __nv_bfloat16 g_qh[NH * SEQ * HD];
__device__ __nv_bfloat16 g_ql[NH * SEQ * HD];
__device__ __nv_bfloat16 g_kh[NH * SEQ * HD];
__device__ __nv_bfloat16 g_kl[NH * SEQ * HD];
__device__ __nv_bfloat16 g_vh[NH * SEQ * HD];
__device__ __nv_bfloat16 g_vl[NH * SEQ * HD];

#define MMA16816(d, a, b)                                              \
    asm volatile(                                                      \
        "mma.sync.aligned.m16n8k16.row.col.f32.bf16.bf16.f32 "         \
        "{%0,%1,%2,%3}, {%4,%5,%6,%7}, {%8,%9}, {%0,%1,%2,%3};"        \
        : "+f"(d[0]), "+f"(d[1]), "+f"(d[2]), "+f"(d[3])               \
        : "r"(a[0]), "r"(a[1]), "r"(a[2]), "r"(a[3]),                  \
          "r"(b[0]), "r"(b[1]))

// ===========================================================================
// HMMA split-bf16 GEMM (unchanged from R6/R9 -- passed at 86 TF/s eff)
// ===========================================================================
#define SPAD 40

__global__ __launch_bounds__(256) void gemm_mma_kernel(
    const float* __restrict__ A, const float* __restrict__ B,
    float* __restrict__ C, int M, int N, int K)
{
    __shared__ __nv_bfloat16 Ah[128 * SPAD];
    __shared__ __nv_bfloat16 Al[128 * SPAD];
    __shared__ __nv_bfloat16 Bh[128 * SPAD];
    __shared__ __nv_bfloat16 Bl[128 * SPAD];

    const int tid  = threadIdx.x;
    const int lane = tid & 31;
    const int w    = tid >> 5;
    const int g    = lane >> 2;
    const int tg   = lane & 3;
    const int wm   = w & 3;
    const int wn   = w >> 2;
    const int m0   = blockIdx.y * 128;
    const int n0   = blockIdx.x * 128;

    float acc[2][8][4];
#pragma unroll
    for (int mt = 0; mt < 2; mt++)
#pragma unroll
        for (int nt = 0; nt < 8; nt++)
#pragma unroll
            for (int r = 0; r < 4; r++) acc[mt][nt][r] = 0.f;

    const int a_f2    = tid & 15;
    const int a_rbase = tid >> 4;
    const int b_n     = tid & 127;
    const int b_kb    = tid >> 7;

    for (int kt = 0; kt < K; kt += 32) {
        __syncthreads();

#pragma unroll
        for (int p = 0; p < 8; p++) {
            int row = p * 16 + a_rbase;
            float2 v = *(const float2*)(A + (size_t)(m0 + row) * K + kt + a_f2 * 2);
            __nv_bfloat16 h0 = __float2bfloat16(v.x);
            __nv_bfloat16 h1 = __float2bfloat16(v.y);
            __nv_bfloat16 l0 = __float2bfloat16(v.x - __bfloat162float(h0));
            __nv_bfloat16 l1 = __float2bfloat16(v.y - __bfloat162float(h1));
            __nv_bfloat162 hh; hh.x = h0; hh.y = h1;
            __nv_bfloat162 ll; ll.x = l0; ll.y = l1;
            *(__nv_bfloat162*)&Ah[row * SPAD + a_f2 * 2] = hh;
            *(__nv_bfloat162*)&Al[row * SPAD + a_f2 * 2] = ll;
        }

#pragma unroll
        for (int p = 0; p < 16; p++) {
            int k = p * 2 + b_kb;
            float v = B[(size_t)(kt + k) * N + n0 + b_n];
            __nv_bfloat16 h = __float2bfloat16(v);
            Bh[b_n * SPAD + k] = h;
            Bl[b_n * SPAD + k] = __float2bfloat16(v - __bfloat162float(h));
        }
        __syncthreads();

#pragma unroll
        for (int ks = 0; ks < 2; ks++) {
            const int kk = ks * 16 + tg * 2;
            uint32_t bh[8][2], bl[8][2];
#pragma unroll
            for (int nt = 0; nt < 8; nt++) {
                int nn = wn * 64 + nt * 8 + g;
                bh[nt][0] = *(uint32_t*)&Bh[nn * SPAD + kk];
                bh[nt][1] = *(uint32_t*)&Bh[nn * SPAD + kk + 8];
                bl[nt][0] = *(uint32_t*)&Bl[nn * SPAD + kk];
                bl[nt][1] = *(uint32_t*)&Bl[nn * SPAD + kk + 8];
            }
#pragma unroll
            for (int mt = 0; mt < 2; mt++) {
                const int rb = wm * 32 + mt * 16;
                uint32_t ah[4], al[4];
                ah[0] = *(uint32_t*)&Ah[(rb + g)     * SPAD + kk];
                ah[1] = *(uint32_t*)&Ah[(rb + g + 8) * SPAD + kk];
                ah[2] = *(uint32_t*)&Ah[(rb + g)     * SPAD + kk + 8];
                ah[3] = *(uint32_t*)&Ah[(rb + g + 8) * SPAD + kk + 8];
                al[0] = *(uint32_t*)&Al[(rb + g)     * SPAD + kk];
                al[1] = *(uint32_t*)&Al[(rb + g + 8) * SPAD + kk];
                al[2] = *(uint32_t*)&Al[(rb + g)     * SPAD + kk + 8];
                al[3] = *(uint32_t*)&Al[(rb + g + 8) * SPAD + kk + 8];
#pragma unroll
                for (int nt = 0; nt < 8; nt++) {
                    MMA16816(acc[mt][nt], ah, bh[nt]);
                    MMA16816(acc[mt][nt], ah, bl[nt]);
                    MMA16816(acc[mt][nt], al, bh[nt]);
                }
            }
        }
    }

#pragma unroll
    for (int mt = 0; mt < 2; mt++) {
        const int row = m0 + wm * 32 + mt * 16 + g;
#pragma unroll
        for (int nt = 0; nt < 8; nt++) {
            const int col = n0 + wn * 64 + nt * 8 + tg * 2;
            *(float2*)(C + (size_t)row * N + col) =
                make_float2(acc[mt][nt][0], acc[mt][nt][1]);
            *(float2*)(C + (size_t)(row + 8) * N + col) =
                make_float2(acc[mt][nt][2], acc[mt][nt][3]);
        }
    }
}

// ---------------------------------------------------------------------------
// RoPE tables
// ---------------------------------------------------------------------------
__global__ __launch_bounds__(256) void rope_table_kernel()
{
    int idx = blockIdx.x * blockDim.x + threadIdx.x;
    if (idx >= SEQ * 32) return;
    int p = idx & 31;
    int l = idx >> 5;
    float inv_freq = powf(10000.0f, -(2.0f * (float)p) / 64.0f);
    float ang = (float)l * inv_freq;
    float s, c;
    sincosf(ang, &s, &c);
    g_cos[idx] = c;
    g_sin[idx] = s;
}

// ---------------------------------------------------------------------------
// RoPE + scatter -> split bf16 hi/lo. Q prescaled by 1/8.
// ---------------------------------------------------------------------------
__device__ __forceinline__ void split_store(__nv_bfloat16* ph, __nv_bfloat16* pl,
                                            size_t idx, float a, float b)
{
    __nv_bfloat16 h0 = __float2bfloat16(a);
    __nv_bfloat16 h1 = __float2bfloat16(b);
    __nv_bfloat162 hh; hh.x = h0; hh.y = h1;
    __nv_bfloat162 ll;
    ll.x = __float2bfloat16(a - __bfloat162float(h0));
    ll.y = __float2bfloat16(b - __bfloat162float(h1));
    *(__nv_bfloat162*)&ph[idx] = hh;
    *(__nv_bfloat162*)&pl[idx] = ll;
}

__global__ __launch_bounds__(256) void rope_scatter_kernel(const float* __restrict__ qkv)
{
    int idx = blockIdx.x * blockDim.x + threadIdx.x;
    if (idx >= SEQ * NH * 32) return;
    int p = idx & 31;
    int h = (idx >> 5) & (NH - 1);
    int l = idx >> 9;

    float c = g_cos[l * 32 + p];
    float s = g_sin[l * 32 + p];

    const float* src = qkv + (size_t)l * (3 * DM);
    int col = h * HD + 2 * p;
    float q0 = src[col],          q1 = src[col + 1];
    float k0 = src[DM + col],     k1 = src[DM + col + 1];
    float v0 = src[2 * DM + col], v1 = src[2 * DM + col + 1];

    float qr0 = (q0 * c - q1 * s) * 0.125f;   // fold 1/sqrt(64)
    float qr1 = (q1 * c + q0 * s) * 0.125f;
    float kr0 = k0 * c - k1 * s;
    float kr1 = k1 * c + k0 * s;

    size_t dst = (size_t)(h * SEQ + l) * HD + 2 * p;
    split_store(g_qh, g_ql, dst, qr0, qr1);
    split_store(g_kh, g_kl, dst, kr0, kr1);
    split_store(g_vh, g_vl, dst, v0, v1);
}

// ---------------------------------------------------------------------------
// HMMA flash attention. CTA = 128 thr (4 warps) = 64-query tile of one head.
// Warp w owns query rows [r0+16w, r0+16w+16). Q A-frags in registers.
// Per 64-key tile: K [key][dim] + V^T [dim][key] in smem (hi/lo bf16).
// PITCH=72 halfwords -> all frag LDS conflict-free; V transpose stores
// conflict-free via (rp = lane) mapping.
// ---------------------------------------------------------------------------
#define PITCH 72

__global__ __launch_bounds__(128) void attn_mma_kernel(
    const __nv_bfloat16* __restrict__ Qh, const __nv_bfloat16* __restrict__ Ql,
    const __nv_bfloat16* __restrict__ Kh, const __nv_bfloat16* __restrict__ Kl,
    const __nv_bfloat16* __restrict__ Vh, const __nv_bfloat16* __restrict__ Vl,
    float* __restrict__ O)
{
    __shared__ __nv_bfloat16 sKh[64 * PITCH];
    __shared__ __nv_bfloat16 sKl[64 * PITCH];
    __shared__ __nv_bfloat16 sVh[64 * PITCH];   // [d][k]
    __shared__ __nv_bfloat16 sVl[64 * PITCH];

    const int tid  = threadIdx.x;
    const int lane = tid & 31;
    const int w    = tid >> 5;
    const int g    = lane >> 2;
    const int tg   = lane & 3;
    const int h    = blockIdx.y;
    const int r0   = blockIdx.x * 64;
    const int qrow = r0 + w * 16 + g;     // row g; row g+8 = qrow+8

    // ---- Q A-frags (held in registers for the whole kernel) ----
    uint32_t qfh[4][4], qfl[4][4];
    {
        const size_t base = (size_t)(h * SEQ + qrow) * HD;
#pragma unroll
        for (int kc = 0; kc < 4; kc++) {
            int k0 = kc * 16 + tg * 2;
            qfh[kc][0] = *(const uint32_t*)&Qh[base + k0];
            qfh[kc][1] = *(const uint32_t*)&Qh[base + 8 * HD + k0];
            qfh[kc][2] = *(const uint32_t*)&Qh[base + k0 + 8];
            qfh[kc][3] = *(const uint32_t*)&Qh[base + 8 * HD + k0 + 8];
            qfl[kc][0] = *(const uint32_t*)&Ql[base + k0];
            qfl[kc][1] = *(const uint32_t*)&Ql[base + 8 * HD + k0];
            qfl[kc][2] = *(const uint32_t*)&Ql[base + k0 + 8];
            qfl[kc][3] = *(const uint32_t*)&Ql[base + 8 * HD + k0 + 8];
        }
    }

    float o[8][4];
#pragma unroll
    for (int nt = 0; nt < 8; nt++)
#pragma unroll
        for (int r = 0; r < 4; r++) o[nt][r] = 0.f;
    float m[2] = {-1e30f, -1e30f};
    float lsum[2] = {0.f, 0.f};

    const int t_hi = r0 >> 6;
    int jmin = r0 - (WIN - 1); if (jmin < 0) jmin = 0;
    const int t_lo = jmin >> 6;

    for (int t = t_hi; t >= t_lo; t--) {
        const int c0 = t * 64;
        __syncthreads();   // previous tile's smem reads complete

        // ---- K tile: [key][dim], uint4 copies ----
#pragma unroll
        for (int i = 0; i < 4; i++) {
            int idx = i * 128 + tid;
            int row = idx >> 3, c8 = idx & 7;
            const size_t gofs = (size_t)(h * SEQ + c0 + row) * HD + c8 * 8;
            *(uint4*)&sKh[row * PITCH + c8 * 8] = *(const uint4*)&Kh[gofs];
            *(uint4*)&sKl[row * PITCH + c8 * 8] = *(const uint4*)&Kl[gofs];
        }
        // ---- V tile transposed: [d][k], conflict-free packed stores ----
        {
            const int rp = tid & 31;        // key row-pair
            const int cq = tid >> 5;        // 0..3
#pragma unroll
            for (int it = 0; it < 2; it++) {
                int c8 = cq + 4 * it;
                const size_t g0 = (size_t)(h * SEQ + c0 + 2 * rp) * HD + c8 * 8;
                uint4 h0 = *(const uint4*)&Vh[g0];
                uint4 h1 = *(const uint4*)&Vh[g0 + HD];
                uint4 l0 = *(const uint4*)&Vl[g0];
                uint4 l1 = *(const uint4*)&Vl[g0 + HD];
                const uint16_t* a0 = (const uint16_t*)&h0;
                const uint16_t* a1 = (const uint16_t*)&h1;
                const uint16_t* b0 = (const uint16_t*)&l0;
                const uint16_t* b1 = (const uint16_t*)&l1;
#pragma unroll
                for (int j = 0; j < 8; j++) {
                    int d = c8 * 8 + j;
                    *(uint32_t*)&sVh[d * PITCH + 2 * rp] =
                        (uint32_t)a0[j] | ((uint32_t)a1[j] << 16);
                    *(uint32_t*)&sVl[d * PITCH + 2 * rp] =
                        (uint32_t)b0[j] | ((uint32_t)b1[j] << 16);
                }
            }
        }
        __syncthreads();

        // ---- S = Q @ K^T ----
        float s[8][4];
#pragma unroll
        for (int nt = 0; nt < 8; nt++)
#pragma unroll
            for (int r = 0; r < 4; r++) s[nt][r] = 0.f;

#pragma unroll
        for (int nt = 0; nt < 8; nt++) {
            const int nb = (nt * 8 + g) * PITCH;
#pragma unroll
            for (int kc = 0; kc < 4; kc++) {
                const int kk = kc * 16 + tg * 2;
                uint32_t bh[2], bl[2];
                bh[0] = *(uint32_t*)&sKh[nb + kk];
                bh[1] = *(uint32_t*)&sKh[nb + kk + 8];
                bl[0] = *(uint32_t*)&sKl[nb + kk];
                bl[1] = *(uint32_t*)&sKl[nb + kk + 8];
                MMA16816(s[nt], qfh[kc], bh);
                MMA16816(s[nt], qfh[kc], bl);
                MMA16816(s[nt], qfl[kc], bh);
            }
        }

        // ---- mask (diagonal + window-edge tiles only) ----
        if (t == t_hi || t_hi - t >= 8) {
#pragma unroll
            for (int nt = 0; nt < 8; nt++)
#pragma unroll
                for (int r = 0; r < 4; r++) {
                    int row = qrow + (r >> 1) * 8;
                    int col = c0 + nt * 8 + tg * 2 + (r & 1);
                    if (col > row || row - col >= WIN) s[nt][r] = -1e30f;
                }
        }

        // ---- online softmax (2 rows per thread, quad shfl reduce) ----
        float p[8][4];
#pragma unroll
        for (int r2 = 0; r2 < 2; r2++) {
            float mx = -1e30f;
#pragma unroll
            for (int nt = 0; nt < 8; nt++)
                mx = fmaxf(mx, fmaxf(s[nt][r2 * 2], s[nt][r2 * 2 + 1]));
            mx = fmaxf(mx, __shfl_xor_sync(0xFFFFFFFFu, mx, 1));
            mx = fmaxf(mx, __shfl_xor_sync(0xFFFFFFFFu, mx, 2));
            float newm = fmaxf(m[r2], mx);
            float corr = __expf(m[r2] - newm);
            m[r2] = newm;
            float rs = 0.f;
#pragma unroll
            for (int nt = 0; nt < 8; nt++) {
                float p0 = __expf(s[nt][r2 * 2]     - newm);
                float p1 = __expf(s[nt][r2 * 2 + 1] - newm);
                p[nt][r2 * 2] = p0; p[nt][r2 * 2 + 1] = p1;
                rs += p0 + p1;
            }
            rs += __shfl_xor_sync(0xFFFFFFFFu, rs, 1);
            rs += __shfl_xor_sync(0xFFFFFFFFu, rs, 2);
            lsum[r2] = lsum[r2] * corr + rs;
#pragma unroll
            for (int nt = 0; nt < 8; nt++) {
                o[nt][r2 * 2]     *= corr;
                o[nt][r2 * 2 + 1] *= corr;
            }
        }

        // ---- P -> A-frags (C-layout == A-layout), split hi/lo ----
        uint32_t pah[4][4], pal[4][4];
#pragma unroll
        for (int kc = 0; kc < 4; kc++) {
#pragma unroll
            for (int r = 0; r < 2; r++) {       // r=0: row g (regs 0,1); r=1: row g+8 (regs 2,3)
                float v0 = p[2 * kc][r * 2],     v1 = p[2 * kc][r * 2 + 1];
                float v2 = p[2 * kc + 1][r * 2], v3 = p[2 * kc + 1][r * 2 + 1];
                __nv_bfloat16 h0 = __float2bfloat16(v0), h1 = __float2bfloat16(v1);
                __nv_bfloat16 h2 = __float2bfloat16(v2), h3 = __float2bfloat16(v3);
                pah[kc][r]     = (uint32_t)*(uint16_t*)&h0 | ((uint32_t)*(uint16_t*)&h1 << 16);
                pah[kc][r + 2] = (uint32_t)*(uint16_t*)&h2 | ((uint32_t)*(uint16_t*)&h3 << 16);
                __nv_bfloat16 e0 = __float2bfloat16(v0 - __bfloat162float(h0));
                __nv_bfloat16 e1 = __float2bfloat16(v1 - __bfloat162float(h1));
                __nv_bfloat16 e2 = __float2bfloat16(v2 - __bfloat162float(h2));
                __nv_bfloat16 e3 = __float2bfloat16(v3 - __bfloat162float(h3));
                pal[kc][r]     = (uint32_t)*(uint16_t*)&e0 | ((uint32_t)*(uint16_t*)&e1 << 16);
                pal[kc][r + 2] = (uint32_t)*(uint16_t*)&e2 | ((uint32_t)*(uint16_t*)&e3 << 16);
            }
        }

        // ---- O += P @ V ----
#pragma unroll
        for (int nt = 0; nt < 8; nt++) {
            const int nb = (nt * 8 + g) * PITCH;
#pragma unroll
            for (int kc = 0; kc < 4; kc++) {
                const int kk = kc * 16 + tg * 2;
                uint32_t bh[2], bl[2];
                bh[0] = *(uint32_t*)&sVh[nb + kk];
                bh[1] = *(uint32_t*)&sVh[nb + kk + 8];
                bl[0] = *(uint32_t*)&sVl[nb + kk];
                bl[1] = *(uint32_t*)&sVl[nb + kk + 8];
                MMA16816(o[nt], pah[kc], bh);
                MMA16816(o[nt], pah[kc], bl);
                MMA16816(o[nt], pal[kc], bh);
            }
        }
    }

    // ---- epilogue: normalize, write [L, DM] ----
    const float inv0 = 1.0f / lsum[0];
    const float inv1 = 1.0f / lsum[1];
#pragma unroll
    for (int nt = 0; nt < 8; nt++) {
        const int col = h * HD + nt * 8 + tg * 2;
        *(float2*)(O + (size_t)qrow * DM + col) =
            make_float2(o[nt][0] * inv0, o[nt][1] * inv0);
        *(float2*)(O + (size_t)(qrow + 8) * DM + col) =
            make_float2(o[nt][2] * inv1, o[nt][3] * inv1);
    }
}

// ---------------------------------------------------------------------------
extern "C" void kernel_launch(void* const* d_in, const int* in_sizes, int n_in,
                              void* d_out, int out_size)
{
    const float* x     = (const float*)d_in[0];
    const float* w_qkv = (const float*)d_in[1];
    const float* w_out = (const float*)d_in[2];
    float* out = (float*)d_out;

    float *p_qkv, *p_att;
    cudaGetSymbolAddress((void**)&p_qkv, g_qkv);
    cudaGetSymbolAddress((void**)&p_att, g_att);
    __nv_bfloat16 *p_qh, *p_ql, *p_kh, *p_kl, *p_vh, *p_vl;
    cudaGetSymbolAddress((void**)&p_qh, g_qh);
    cudaGetSymbolAddress((void**)&p_ql, g_ql);
    cudaGetSymbolAddress((void**)&p_kh, g_kh);
    cudaGetSymbolAddress((void**)&p_kl, g_kl);
    cudaGetSymbolAddress((void**)&p_vh, g_vh);
    cudaGetSymbolAddress((void**)&p_vl, g_vl);

    rope_table_kernel<<<(SEQ * 32 + 255) / 256, 256>>>();

    // 1) qkv = x @ w_qkv  (HMMA split-bf16)
    gemm_mma_kernel<<<dim3(3 * DM / 128, SEQ / 128), 256>>>(x, w_qkv, p_qkv, SEQ, 3 * DM, DM);

    // 2) RoPE + split-bf16 scatter
    int total = SEQ * NH * 32;
    rope_scatter_kernel<<<(total + 255) / 256, 256>>>(p_qkv);

    // 3) HMMA flash attention
    attn_mma_kernel<<<dim3(SEQ / 64, NH), 128>>>(p_qh, p_ql, p_kh, p_kl, p_vh, p_vl, p_att);

    // 4) out = att @ w_out  (HMMA split-bf16)
    gemm_mma_kernel<<<dim3(DM / 128, SEQ / 128), 256>>>(p_att, w_out, out, SEQ, DM, DM);
}

// round 15
// speedup vs baseline: 2.1542x; 1.0642x over previous
#include <cuda_runtime.h>
#include <cuda_bf16.h>
#include <math.h>
#include <cstdint>

#define SEQ 4096
#define DM 1024
#define NH 16
#define HD 64
#define WIN 512

// Scratch (allocation-free rule: __device__ globals)
__device__ float g_qkv[SEQ * 3 * DM];
__device__ float g_cos[SEQ * 32];
__device__ float g_sin[SEQ * 32];
// split-bf16 operands
__device__ __nv_bfloat16 g_xh[SEQ * DM],      g_xl[SEQ * DM];        // x split
__device__ __nv_bfloat16 g_wqh[3 * DM * DM],  g_wql[3 * DM * DM];    // w_qkv^T split [n][k]
__device__ __nv_bfloat16 g_woh[DM * DM],      g_wol[DM * DM];        // w_out^T split [n][k]
__device__ __nv_bfloat16 g_atth[SEQ * DM],    g_attl[SEQ * DM];      // attention out split
// split-bf16 Q/K/V, head-major [h][l][64]; Q prescaled by 1/8
__device__ __nv_bfloat16 g_qh[NH * SEQ * HD], g_ql[NH * SEQ * HD];
__device__ __nv_bfloat16 g_kh[NH * SEQ * HD], g_kl[NH * SEQ * HD];
__device__ __nv_bfloat16 g_vh[NH * SEQ * HD], g_vl[NH * SEQ * HD];

#define MMA16816(d, a, b)                                              \
    asm volatile(                                                      \
        "mma.sync.aligned.m16n8k16.row.col.f32.bf16.bf16.f32 "         \
        "{%0,%1,%2,%3}, {%4,%5,%6,%7}, {%8,%9}, {%0,%1,%2,%3};"        \
        : "+f"(d[0]), "+f"(d[1]), "+f"(d[2]), "+f"(d[3])               \
        : "r"(a[0]), "r"(a[1]), "r"(a[2]), "r"(a[3]),                  \
          "r"(b[0]), "r"(b[1]))

__device__ __forceinline__ uint32_t smem_u32(const void* p) {
    uint32_t a;
    asm("{ .reg .u64 t; cvta.to.shared.u64 t, %1; cvt.u32.u64 %0, t; }" : "=r"(a) : "l"(p));
    return a;
}
__device__ __forceinline__ void cp_async16(uint32_t saddr, const void* g) {
    asm volatile("cp.async.cg.shared.global [%0], [%1], 16;" :: "r"(saddr), "l"(g));
}
#define CP_COMMIT() asm volatile("cp.async.commit_group;")
#define CP_WAIT0()  asm volatile("cp.async.wait_group 0;")
#define CP_WAIT1()  asm volatile("cp.async.wait_group 1;")

__device__ __forceinline__ void split_store(__nv_bfloat16* ph, __nv_bfloat16* pl,
                                            size_t idx, float a, float b)
{
    __nv_bfloat16 h0 = __float2bfloat16(a);
    __nv_bfloat16 h1 = __float2bfloat16(b);
    __nv_bfloat162 hh; hh.x = h0; hh.y = h1;
    __nv_bfloat162 ll;
    ll.x = __float2bfloat16(a - __bfloat162float(h0));
    ll.y = __float2bfloat16(b - __bfloat162float(h1));
    *(__nv_bfloat162*)&ph[idx] = hh;
    *(__nv_bfloat162*)&pl[idx] = ll;
}

// ===========================================================================
// Pre-split kernels (run once per launch; ~25 us total)
// ===========================================================================
__global__ __launch_bounds__(256) void split_x_kernel(const float* __restrict__ x)
{
    int idx = blockIdx.x * blockDim.x + threadIdx.x;   // float2 index
    if (idx >= SEQ * DM / 2) return;
    float2 v = ((const float2*)x)[idx];
    split_store(g_xh, g_xl, (size_t)idx * 2, v.x, v.y);
}

// W[K][N] fp32 -> Th/Tl[N][K] bf16 (transposed split), 32x32 smem tiles
__global__ __launch_bounds__(256) void tsplit_kernel(
    const float* __restrict__ W, __nv_bfloat16* __restrict__ Th,
    __nv_bfloat16* __restrict__ Tl, int K, int N)
{
    __shared__ float tile[32][33];
    const int n0 = blockIdx.x * 32;
    const int k0 = blockIdx.y * 32;
    const int tx = threadIdx.x, ty = threadIdx.y;
#pragma unroll
    for (int i = 0; i < 4; i++)
        tile[ty + i * 8][tx] = W[(size_t)(k0 + ty + i * 8) * N + n0 + tx];
    __syncthreads();
#pragma unroll
    for (int i = 0; i < 4; i++) {
        int n = n0 + ty + i * 8;
        int k = k0 + tx;
        float v = tile[tx][ty + i * 8];
        __nv_bfloat16 h = __float2bfloat16(v);
        Th[(size_t)n * K + k] = h;
        Tl[(size_t)n * K + k] = __float2bfloat16(v - __bfloat162float(h));
    }
}

// ===========================================================================
// Double-buffered bf16 HMMA GEMM: C[M,N] = (Ah+Al)[M,K] @ (Bh+Bl)^T
// A hi/lo [m][k], B hi/lo [n][k] (pre-transposed). 3-term split product.
// 256 thr (8 warps, 4m x 2n), 128x128 tile, BK=32, cp.async 2-stage.
// ===========================================================================
#define GPITCH 40
#define ASTRIDE (128 * GPITCH)          // bf16 elems per array
#define STAGE   (4 * ASTRIDE)           // elems per stage
#define GEMM_SMEM (2 * STAGE * 2)       // bytes = 81920

__global__ __launch_bounds__(256) void gemm_bf16_kernel(
    const __nv_bfloat16* __restrict__ Ahg, const __nv_bfloat16* __restrict__ Alg,
    const __nv_bfloat16* __restrict__ Bhg, const __nv_bfloat16* __restrict__ Blg,
    float* __restrict__ C, int M, int N, int K)
{
    extern __shared__ __nv_bfloat16 sm[];
    const uint32_t sb = smem_u32(sm);

    const int tid  = threadIdx.x;
    const int lane = tid & 31;
    const int w    = tid >> 5;
    const int g    = lane >> 2;
    const int tg   = lane & 3;
    const int wm   = w & 3;
    const int wn   = w >> 2;
    const int m0   = blockIdx.y * 128;
    const int n0   = blockIdx.x * 128;

    float acc[2][8][4];
#pragma unroll
    for (int mt = 0; mt < 2; mt++)
#pragma unroll
        for (int nt = 0; nt < 8; nt++)
#pragma unroll
            for (int r = 0; r < 4; r++) acc[mt][nt][r] = 0.f;

    // cp.async stage loader: 8 x 16B per thread
    const int l_row = tid >> 2;
    const int l_c8  = (tid & 3) * 8;
#define LOAD_STAGE(st, kt)                                                          \
    do {                                                                            \
        uint32_t base = sb + (uint32_t)(st) * STAGE * 2;                            \
        _Pragma("unroll")                                                           \
        for (int r = 0; r < 2; r++) {                                               \
            int row = l_row + r * 64;                                               \
            uint32_t doff = (uint32_t)(row * GPITCH + l_c8) * 2;                    \
            size_t ao = (size_t)(m0 + row) * K + (kt) + l_c8;                       \
            size_t bo = (size_t)(n0 + row) * K + (kt) + l_c8;                       \
            cp_async16(base + doff,                   Ahg + ao);                    \
            cp_async16(base + ASTRIDE * 2 + doff,     Alg + ao);                    \
            cp_async16(base + 2 * ASTRIDE * 2 + doff, Bhg + bo);                    \
            cp_async16(base + 3 * ASTRIDE * 2 + doff, Blg + bo);                    \
        }                                                                           \
    } while (0)

    const int nch = K >> 5;
    LOAD_STAGE(0, 0);
    CP_COMMIT();

    for (int ch = 0; ch < nch; ch++) {
        if (ch + 1 < nch) {
            LOAD_STAGE((ch + 1) & 1, (ch + 1) * 32);
            CP_COMMIT();
            CP_WAIT1();
        } else {
            CP_WAIT0();
        }
        __syncthreads();

        const __nv_bfloat16* sAh = sm + (ch & 1) * STAGE;
        const __nv_bfloat16* sAl = sAh + ASTRIDE;
        const __nv_bfloat16* sBh = sAl + ASTRIDE;
        const __nv_bfloat16* sBl = sBh + ASTRIDE;

#pragma unroll
        for (int ks = 0; ks < 2; ks++) {
            const int kk = ks * 16 + tg * 2;
            uint32_t bh[8][2], bl[8][2];
#pragma unroll
            for (int nt = 0; nt < 8; nt++) {
                int nn = wn * 64 + nt * 8 + g;
                bh[nt][0] = *(const uint32_t*)&sBh[nn * GPITCH + kk];
                bh[nt][1] = *(const uint32_t*)&sBh[nn * GPITCH + kk + 8];
                bl[nt][0] = *(const uint32_t*)&sBl[nn * GPITCH + kk];
                bl[nt][1] = *(const uint32_t*)&sBl[nn * GPITCH + kk + 8];
            }
#pragma unroll
            for (int mt = 0; mt < 2; mt++) {
                const int rb = wm * 32 + mt * 16;
                uint32_t ah[4], al[4];
                ah[0] = *(const uint32_t*)&sAh[(rb + g)     * GPITCH + kk];
                ah[1] = *(const uint32_t*)&sAh[(rb + g + 8) * GPITCH + kk];
                ah[2] = *(const uint32_t*)&sAh[(rb + g)     * GPITCH + kk + 8];
                ah[3] = *(const uint32_t*)&sAh[(rb + g + 8) * GPITCH + kk + 8];
                al[0] = *(const uint32_t*)&sAl[(rb + g)     * GPITCH + kk];
                al[1] = *(const uint32_t*)&sAl[(rb + g + 8) * GPITCH + kk];
                al[2] = *(const uint32_t*)&sAl[(rb + g)     * GPITCH + kk + 8];
                al[3] = *(const uint32_t*)&sAl[(rb + g + 8) * GPITCH + kk + 8];
#pragma unroll
                for (int nt = 0; nt < 8; nt++) {
                    MMA16816(acc[mt][nt], ah, bh[nt]);
                    MMA16816(acc[mt][nt], ah, bl[nt]);
                    MMA16816(acc[mt][nt], al, bh[nt]);
                }
            }
        }
        __syncthreads();
    }

#pragma unroll
    for (int mt = 0; mt < 2; mt++) {
        const int row = m0 + wm * 32 + mt * 16 + g;
#pragma unroll
        for (int nt = 0; nt < 8; nt++) {
            const int col = n0 + wn * 64 + nt * 8 + tg * 2;
            *(float2*)(C + (size_t)row * N + col) =
                make_float2(acc[mt][nt][0], acc[mt][nt][1]);
            *(float2*)(C + (size_t)(row + 8) * N + col) =
                make_float2(acc[mt][nt][2], acc[mt][nt][3]);
        }
    }
}

// ---------------------------------------------------------------------------
// RoPE tables
// ---------------------------------------------------------------------------
__global__ __launch_bounds__(256) void rope_table_kernel()
{
    int idx = blockIdx.x * blockDim.x + threadIdx.x;
    if (idx >= SEQ * 32) return;
    int p = idx & 31;
    int l = idx >> 5;
    float inv_freq = powf(10000.0f, -(2.0f * (float)p) / 64.0f);
    float ang = (float)l * inv_freq;
    float s, c;
    sincosf(ang, &s, &c);
    g_cos[idx] = c;
    g_sin[idx] = s;
}

// ---------------------------------------------------------------------------
// RoPE + scatter -> split bf16 hi/lo. Q prescaled by 1/8.
// ---------------------------------------------------------------------------
__global__ __launch_bounds__(256) void rope_scatter_kernel(const float* __restrict__ qkv)
{
    int idx = blockIdx.x * blockDim.x + threadIdx.x;
    if (idx >= SEQ * NH * 32) return;
    int p = idx & 31;
    int h = (idx >> 5) & (NH - 1);
    int l = idx >> 9;

    float c = g_cos[l * 32 + p];
    float s = g_sin[l * 32 + p];

    const float* src = qkv + (size_t)l * (3 * DM);
    int col = h * HD + 2 * p;
    float q0 = src[col],          q1 = src[col + 1];
    float k0 = src[DM + col],     k1 = src[DM + col + 1];
    float v0 = src[2 * DM + col], v1 = src[2 * DM + col + 1];

    float qr0 = (q0 * c - q1 * s) * 0.125f;
    float qr1 = (q1 * c + q0 * s) * 0.125f;
    float kr0 = k0 * c - k1 * s;
    float kr1 = k1 * c + k0 * s;

    size_t dst = (size_t)(h * SEQ + l) * HD + 2 * p;
    split_store(g_qh, g_ql, dst, qr0, qr1);
    split_store(g_kh, g_kl, dst, kr0, kr1);
    split_store(g_vh, g_vl, dst, v0, v1);
}

// ---------------------------------------------------------------------------
// HMMA flash attention (R9 design). Epilogue now writes split-bf16 att.
// ---------------------------------------------------------------------------
#define PITCH 72

__global__ __launch_bounds__(128) void attn_mma_kernel(
    const __nv_bfloat16* __restrict__ Qh, const __nv_bfloat16* __restrict__ Ql,
    const __nv_bfloat16* __restrict__ Kh, const __nv_bfloat16* __restrict__ Kl,
    const __nv_bfloat16* __restrict__ Vh, const __nv_bfloat16* __restrict__ Vl,
    __nv_bfloat16* __restrict__ Oh, __nv_bfloat16* __restrict__ Ol)
{
    __shared__ __nv_bfloat16 sKh[64 * PITCH];
    __shared__ __nv_bfloat16 sKl[64 * PITCH];
    __shared__ __nv_bfloat16 sVh[64 * PITCH];   // [d][k]
    __shared__ __nv_bfloat16 sVl[64 * PITCH];

    const int tid  = threadIdx.x;
    const int lane = tid & 31;
    const int w    = tid >> 5;
    const int g    = lane >> 2;
    const int tg   = lane & 3;
    const int h    = blockIdx.y;
    const int r0   = blockIdx.x * 64;
    const int qrow = r0 + w * 16 + g;

    uint32_t qfh[4][4], qfl[4][4];
    {
        const size_t base = (size_t)(h * SEQ + qrow) * HD;
#pragma unroll
        for (int kc = 0; kc < 4; kc++) {
            int k0 = kc * 16 + tg * 2;
            qfh[kc][0] = *(const uint32_t*)&Qh[base + k0];
            qfh[kc][1] = *(const uint32_t*)&Qh[base + 8 * HD + k0];
            qfh[kc][2] = *(const uint32_t*)&Qh[base + k0 + 8];
            qfh[kc][3] = *(const uint32_t*)&Qh[base + 8 * HD + k0 + 8];
            qfl[kc][0] = *(const uint32_t*)&Ql[base + k0];
            qfl[kc][1] = *(const uint32_t*)&Ql[base + 8 * HD + k0];
            qfl[kc][2] = *(const uint32_t*)&Ql[base + k0 + 8];
            qfl[kc][3] = *(const uint32_t*)&Ql[base + 8 * HD + k0 + 8];
        }
    }

    float o[8][4];
#pragma unroll
    for (int nt = 0; nt < 8; nt++)
#pragma unroll
        for (int r = 0; r < 4; r++) o[nt][r] = 0.f;
    float m[2] = {-1e30f, -1e30f};
    float lsum[2] = {0.f, 0.f};

    const int t_hi = r0 >> 6;
    int jmin = r0 - (WIN - 1); if (jmin < 0) jmin = 0;
    const int t_lo = jmin >> 6;

    for (int t = t_hi; t >= t_lo; t--) {
        const int c0 = t * 64;
        __syncthreads();

#pragma unroll
        for (int i = 0; i < 4; i++) {
            int idx = i * 128 + tid;
            int row = idx >> 3, c8 = idx & 7;
            const size_t gofs = (size_t)(h * SEQ + c0 + row) * HD + c8 * 8;
            *(uint4*)&sKh[row * PITCH + c8 * 8] = *(const uint4*)&Kh[gofs];
            *(uint4*)&sKl[row * PITCH + c8 * 8] = *(const uint4*)&Kl[gofs];
        }
        {
            const int rp = tid & 31;
            const int cq = tid >> 5;
#pragma unroll
            for (int it = 0; it < 2; it++) {
                int c8 = cq + 4 * it;
                const size_t g0 = (size_t)(h * SEQ + c0 + 2 * rp) * HD + c8 * 8;
                uint4 h0 = *(const uint4*)&Vh[g0];
                uint4 h1 = *(const uint4*)&Vh[g0 + HD];
                uint4 l0 = *(const uint4*)&Vl[g0];
                uint4 l1 = *(const uint4*)&Vl[g0 + HD];
                const uint16_t* a0 = (const uint16_t*)&h0;
                const uint16_t* a1 = (const uint16_t*)&h1;
                const uint16_t* b0 = (const uint16_t*)&l0;
                const uint16_t* b1 = (const uint16_t*)&l1;
#pragma unroll
                for (int j = 0; j < 8; j++) {
                    int d = c8 * 8 + j;
                    *(uint32_t*)&sVh[d * PITCH + 2 * rp] =
                        (uint32_t)a0[j] | ((uint32_t)a1[j] << 16);
                    *(uint32_t*)&sVl[d * PITCH + 2 * rp] =
                        (uint32_t)b0[j] | ((uint32_t)b1[j] << 16);
                }
            }
        }
        __syncthreads();

        float s[8][4];
#pragma unroll
        for (int nt = 0; nt < 8; nt++)
#pragma unroll
            for (int r = 0; r < 4; r++) s[nt][r] = 0.f;

#pragma unroll
        for (int nt = 0; nt < 8; nt++) {
            const int nb = (nt * 8 + g) * PITCH;
#pragma unroll
            for (int kc = 0; kc < 4; kc++) {
                const int kk = kc * 16 + tg * 2;
                uint32_t bh[2], bl[2];
                bh[0] = *(uint32_t*)&sKh[nb + kk];
                bh[1] = *(uint32_t*)&sKh[nb + kk + 8];
                bl[0] = *(uint32_t*)&sKl[nb + kk];
                bl[1] = *(uint32_t*)&sKl[nb + kk + 8];
                MMA16816(s[nt], qfh[kc], bh);
                MMA16816(s[nt], qfh[kc], bl);
                MMA16816(s[nt], qfl[kc], bh);
            }
        }

        if (t == t_hi || t_hi - t >= 8) {
#pragma unroll
            for (int nt = 0; nt < 8; nt++)
#pragma unroll
                for (int r = 0; r < 4; r++) {
                    int row = qrow + (r >> 1) * 8;
                    int col = c0 + nt * 8 + tg * 2 + (r & 1);
                    if (col > row || row - col >= WIN) s[nt][r] = -1e30f;
                }
        }

        float p[8][4];
#pragma unroll
        for (int r2 = 0; r2 < 2; r2++) {
            float mx = -1e30f;
#pragma unroll
            for (int nt = 0; nt < 8; nt++)
                mx = fmaxf(mx, fmaxf(s[nt][r2 * 2], s[nt][r2 * 2 + 1]));
            mx = fmaxf(mx, __shfl_xor_sync(0xFFFFFFFFu, mx, 1));
            mx = fmaxf(mx, __shfl_xor_sync(0xFFFFFFFFu, mx, 2));
            float newm = fmaxf(m[r2], mx);
            float corr = __expf(m[r2] - newm);
            m[r2] = newm;
            float rs = 0.f;
#pragma unroll
            for (int nt = 0; nt < 8; nt++) {
                float p0 = __expf(s[nt][r2 * 2]     - newm);
                float p1 = __expf(s[nt][r2 * 2 + 1] - newm);
                p[nt][r2 * 2] = p0; p[nt][r2 * 2 + 1] = p1;
                rs += p0 + p1;
            }
            rs += __shfl_xor_sync(0xFFFFFFFFu, rs, 1);
            rs += __shfl_xor_sync(0xFFFFFFFFu, rs, 2);
            lsum[r2] = lsum[r2] * corr + rs;
#pragma unroll
            for (int nt = 0; nt < 8; nt++) {
                o[nt][r2 * 2]     *= corr;
                o[nt][r2 * 2 + 1] *= corr;
            }
        }

        uint32_t pah[4][4], pal[4][4];
#pragma unroll
        for (int kc = 0; kc < 4; kc++) {
#pragma unroll
            for (int r = 0; r < 2; r++) {
                float v0 = p[2 * kc][r * 2],     v1 = p[2 * kc][r * 2 + 1];
                float v2 = p[2 * kc + 1][r * 2], v3 = p[2 * kc + 1][r * 2 + 1];
                __nv_bfloat16 h0 = __float2bfloat16(v0), h1 = __float2bfloat16(v1);
                __nv_bfloat16 h2 = __float2bfloat16(v2), h3 = __float2bfloat16(v3);
                pah[kc][r]     = (uint32_t)*(uint16_t*)&h0 | ((uint32_t)*(uint16_t*)&h1 << 16);
                pah[kc][r + 2] = (uint32_t)*(uint16_t*)&h2 | ((uint32_t)*(uint16_t*)&h3 << 16);
                __nv_bfloat16 e0 = __float2bfloat16(v0 - __bfloat162float(h0));
                __nv_bfloat16 e1 = __float2bfloat16(v1 - __bfloat162float(h1));
                __nv_bfloat16 e2 = __float2bfloat16(v2 - __bfloat162float(h2));
                __nv_bfloat16 e3 = __float2bfloat16(v3 - __bfloat162float(h3));
                pal[kc][r]     = (uint32_t)*(uint16_t*)&e0 | ((uint32_t)*(uint16_t*)&e1 << 16);
                pal[kc][r + 2] = (uint32_t)*(uint16_t*)&e2 | ((uint32_t)*(uint16_t*)&e3 << 16);
            }
        }

#pragma unroll
        for (int nt = 0; nt < 8; nt++) {
            const int nb = (nt * 8 + g) * PITCH;
#pragma unroll
            for (int kc = 0; kc < 4; kc++) {
                const int kk = kc * 16 + tg * 2;
                uint32_t bh[2], bl[2];
                bh[0] = *(uint32_t*)&sVh[nb + kk];
                bh[1] = *(uint32_t*)&sVh[nb + kk + 8];
                bl[0] = *(uint32_t*)&sVl[nb + kk];
                bl[1] = *(uint32_t*)&sVl[nb + kk + 8];
                MMA16816(o[nt], pah[kc], bh);
                MMA16816(o[nt], pah[kc], bl);
                MMA16816(o[nt], pal[kc], bh);
            }
        }
    }

    // ---- epilogue: normalize, split-bf16 write [L, DM] ----
    const float inv0 = 1.0f / lsum[0];
    const float inv1 = 1.0f / lsum[1];
#pragma unroll
    for (int nt = 0; nt < 8; nt++) {
        const int col = h * HD + nt * 8 + tg * 2;
        split_store(Oh, Ol, (size_t)qrow * DM + col,
                    o[nt][0] * inv0, o[nt][1] * inv0);
        split_store(Oh, Ol, (size_t)(qrow + 8) * DM + col,
                    o[nt][2] * inv1, o[nt][3] * inv1);
    }
}

// ---------------------------------------------------------------------------
extern "C" void kernel_launch(void* const* d_in, const int* in_sizes, int n_in,
                              void* d_out, int out_size)
{
    const float* x     = (const float*)d_in[0];
    const float* w_qkv = (const float*)d_in[1];
    const float* w_out = (const float*)d_in[2];
    float* out = (float*)d_out;

    float* p_qkv;
    cudaGetSymbolAddress((void**)&p_qkv, g_qkv);
    __nv_bfloat16 *p_xh, *p_xl, *p_wqh, *p_wql, *p_woh, *p_wol, *p_atth, *p_attl;
    __nv_bfloat16 *p_qh, *p_ql, *p_kh, *p_kl, *p_vh, *p_vl;
    cudaGetSymbolAddress((void**)&p_xh,  g_xh);
    cudaGetSymbolAddress((void**)&p_xl,  g_xl);
    cudaGetSymbolAddress((void**)&p_wqh, g_wqh);
    cudaGetSymbolAddress((void**)&p_wql, g_wql);
    cudaGetSymbolAddress((void**)&p_woh, g_woh);
    cudaGetSymbolAddress((void**)&p_wol, g_wol);
    cudaGetSymbolAddress((void**)&p_atth, g_atth);
    cudaGetSymbolAddress((void**)&p_attl, g_attl);
    cudaGetSymbolAddress((void**)&p_qh, g_qh);
    cudaGetSymbolAddress((void**)&p_ql, g_ql);
    cudaGetSymbolAddress((void**)&p_kh, g_kh);
    cudaGetSymbolAddress((void**)&p_kl, g_kl);
    cudaGetSymbolAddress((void**)&p_vh, g_vh);
    cudaGetSymbolAddress((void**)&p_vl, g_vl);

    cudaFuncSetAttribute(gemm_bf16_kernel,
                         cudaFuncAttributeMaxDynamicSharedMemorySize, GEMM_SMEM);

    rope_table_kernel<<<(SEQ * 32 + 255) / 256, 256>>>();
    split_x_kernel<<<(SEQ * DM / 2 + 255) / 256, 256>>>(x);
    tsplit_kernel<<<dim3(3 * DM / 32, DM / 32), dim3(32, 8)>>>(w_qkv, p_wqh, p_wql, DM, 3 * DM);
    tsplit_kernel<<<dim3(DM / 32, DM / 32), dim3(32, 8)>>>(w_out, p_woh, p_wol, DM, DM);

    // 1) qkv = x @ w_qkv
    gemm_bf16_kernel<<<dim3(3 * DM / 128, SEQ / 128), 256, GEMM_SMEM>>>(
        p_xh, p_xl, p_wqh, p_wql, p_qkv, SEQ, 3 * DM, DM);

    // 2) RoPE + split scatter
    int total = SEQ * NH * 32;
    rope_scatter_kernel<<<(total + 255) / 256, 256>>>(p_qkv);

    // 3) HMMA flash attention (emits split-bf16 att)
    attn_mma_kernel<<<dim3(SEQ / 64, NH), 128>>>(p_qh, p_ql, p_kh, p_kl, p_vh, p_vl,
                                                 p_atth, p_attl);

    // 4) out = att @ w_out
    gemm_bf16_kernel<<<dim3(DM / 128, SEQ / 128), 256, GEMM_SMEM>>>(
        p_atth, p_attl, p_woh, p_wol, out, SEQ, DM, DM);
}